// round 7
// baseline (speedup 1.0000x reference)
#include <cuda_runtime.h>
#include <cuda_fp16.h>

// out[b,o] = max_k min(x[b,k], w[k,o])  (STE forward == hard max-min)
// x: [B,512] f32 uniform[0,1), w: [512,512] f32, out f32.
//
// Candidate algorithm: out[b,:] is a.s. determined by the top x values of
// row b. Tier-1: x >= 0.875 (~64 cands). Tier-2 (x in [0.78,0.875)) for
// certificate failures (~3e-4). Exact fp32 scan as last resort.
//
// R7: K-split. 256 threads/block, one b row. Thread halves split the
// candidate list for the same 4 outputs; partials combined via smem.
// 8192 warps (55/SM) at 4-output LDG.64 economics. Candidate array is
// zero-padded to a multiple of 16 -> branchless batch loop (min(0,w)=0
// can never raise a max over nonnegative inputs).

#define KDIM 512
#define ODIM 512
#define O2   256
#define NT   256          // 2 halves x 128 lanes; lane owns outputs [4L,4L+4)
#define CUT1 0.875f
#define CUT2 0.78f
#define EPS  1e-3f
#define C1MAX 160         // multiple of 16
#define C2MAX 160

__device__ __half2 g_wh[KDIM * O2];   // [k][o2]; row = 1KB = 128 uint2

__global__ void packw_kernel(const float* __restrict__ w)
{
    int i = blockIdx.x * blockDim.x + threadIdx.x;    // 131072
    if (i < KDIM * O2) {
        float2 v = reinterpret_cast<const float2*>(w)[i];
        g_wh[i] = __floats2half2_rn(v.x, v.y);
    }
}

__global__ __launch_bounds__(NT)
void maxmin_kernel(const float* __restrict__ x,
                   const float* __restrict__ w,
                   float* __restrict__ out)
{
    __shared__ float xs[KDIM];
    __shared__ uint2 c1[C1MAX];       // {half2-splat(x) bits, k*128 (uint2 idx)}
    __shared__ uint2 c2[C2MAX];
    __shared__ uint2 pr[NT];          // per-thread partial accs (2x half2)
    __shared__ int   s_n1, s_n2, s_ovf;

    const int b    = blockIdx.x;
    const int tid  = threadIdx.x;
    const int half = tid >> 7;        // candidate-split half
    const int lane = tid & 127;       // output group: owns outputs [4*lane, 4*lane+4)

    if (tid == 0) { s_n1 = 0; s_n2 = 0; s_ovf = 0; }
    // zero candidate arrays (padding entries must be harmless zeros)
    if (tid < C1MAX) c1[tid] = make_uint2(0u, 0u);
    if (tid < C2MAX) c2[tid] = make_uint2(0u, 0u);
    __syncthreads();

    // ---- stage x row (fp32, for fallback) + threshold selection (2 k/thr) ----
    {
        float2 v = reinterpret_cast<const float2*>(x + (size_t)b * KDIM)[tid];
        reinterpret_cast<float2*>(xs)[tid] = v;
        float e[2] = {v.x, v.y};
#pragma unroll
        for (int q = 0; q < 2; q++) {
            float xv = e[q];
            if (xv >= CUT2) {
                int k = tid * 2 + q;
                __half   h  = __float2half_rn(xv);
                __half2  h2 = __halves2half2(h, h);
                unsigned hb = *reinterpret_cast<const unsigned*>(&h2);
                if (xv >= CUT1) {
                    int p = atomicAdd(&s_n1, 1);
                    if (p < C1MAX) c1[p] = make_uint2(hb, (unsigned)(k * 128));
                    else           s_ovf = 1;
                } else {
                    int p = atomicAdd(&s_n2, 1);
                    if (p < C2MAX) c2[p] = make_uint2(hb, (unsigned)(k * 128));
                    else           s_ovf = 1;
                }
            }
        }
    }
    __syncthreads();

    const int cnt1 = s_n1;
    const int cnt2 = (s_n2 < C2MAX) ? s_n2 : C2MAX;
    const int ovf  = s_ovf;
    const int n1r  = (cnt1 + 15) & ~15;     // zero-padded length (<= C1MAX)

    const uint2* wu = reinterpret_cast<const uint2*>(g_wh);

    __half2 a0 = __float2half2_rn(0.0f);    // inputs >= 0: 0 is a safe -inf
    __half2 a1 = a0;

    if (!ovf) {
        // this half processes batches [t0, t0+8) at t0 = half*8, step 16
        for (int t0 = half * 8; t0 < n1r; t0 += 16) {
            uint2    wv[8];
            unsigned xb[8];
#pragma unroll
            for (int u = 0; u < 8; u++) {
                uint2 c = c1[t0 + u];       // broadcast LDS.64
                xb[u] = c.x;
                wv[u] = wu[c.y + lane];     // LDG.64 (zero cand -> harmless)
            }
#pragma unroll
            for (int u = 0; u < 8; u++) {
                __half2 xv = *reinterpret_cast<__half2*>(&xb[u]);
                a0 = __hmax2(a0, __hmin2(xv, *reinterpret_cast<__half2*>(&wv[u].x)));
                a1 = __hmax2(a1, __hmin2(xv, *reinterpret_cast<__half2*>(&wv[u].y)));
            }
        }
    }

    // ---- combine the two candidate-halves through smem ----
    pr[tid] = make_uint2(*reinterpret_cast<unsigned*>(&a0),
                         *reinterpret_cast<unsigned*>(&a1));
    __syncthreads();

    if (tid < 128) {
        uint2 other = pr[tid + 128];
        a0 = __hmax2(a0, *reinterpret_cast<__half2*>(&other.x));
        a1 = __hmax2(a1, *reinterpret_cast<__half2*>(&other.y));

        float r[4];
        r[0] = __low2float(a0); r[1] = __high2float(a0);
        r[2] = __low2float(a1); r[3] = __high2float(a1);

        // ---- tier-2 extension (rare; any of 4 outputs failing cert) ----
        bool fail1 = false;
#pragma unroll
        for (int j = 0; j < 4; j++) fail1 |= (r[j] < CUT1 + EPS);

        if (!ovf && fail1) {
            for (int t = 0; t < cnt2; t++) {
                uint2 c = c2[t];
                uint2 wv = wu[c.y + lane];
                __half2 xv = *reinterpret_cast<__half2*>(&c.x);
                a0 = __hmax2(a0, __hmin2(xv, *reinterpret_cast<__half2*>(&wv.x)));
                a1 = __hmax2(a1, __hmin2(xv, *reinterpret_cast<__half2*>(&wv.y)));
            }
            r[0] = __low2float(a0); r[1] = __high2float(a0);
            r[2] = __low2float(a1); r[3] = __high2float(a1);
        }

        // ---- exact fp32 fallback (essentially never for uniform data) ----
#pragma unroll
        for (int j = 0; j < 4; j++) {
            if (ovf || r[j] < CUT2 + EPS) {
                int o = lane * 4 + j;
                float rr = 0.0f;
#pragma unroll 4
                for (int k = 0; k < KDIM; k++)
                    rr = fmaxf(rr, fminf(xs[k], w[(size_t)k * ODIM + o]));
                r[j] = rr;
            }
        }

        reinterpret_cast<float4*>(out + (size_t)b * ODIM)[lane] =
            make_float4(r[0], r[1], r[2], r[3]);
    }
}

extern "C" void kernel_launch(void* const* d_in, const int* in_sizes, int n_in,
                              void* d_out, int out_size)
{
    const float* x = (const float*)d_in[0];   // [B, 512]
    const float* w = (const float*)d_in[1];   // [512, 512]
    float* out = (float*)d_out;

    int B = in_sizes[0] / KDIM;               // 1024

    packw_kernel<<<(KDIM * O2 + 255) / 256, 256>>>(w);
    maxmin_kernel<<<B, NT>>>(x, w, out);
}